// round 1
// baseline (speedup 1.0000x reference)
#include <cuda_runtime.h>
#include <cuda_bf16.h>
#include <math.h>
#include <float.h>

// Problem constants
#define BATCH 8
#define SEQ   2048
#define DMODEL 1024
#define EPS_ENT 1e-10f
#define EPS_LN  1e-5f

// ---------------- scratch (allocation-free: __device__ globals) ----------------
__device__ float g_scores[(size_t)BATCH * SEQ * SEQ];     // 134 MB: scores -> attention probs (in-place)
__device__ float g_attout[(size_t)BATCH * SEQ * DMODEL];  // 67 MB: attention @ V
__device__ float g_rowent[(size_t)BATCH * SEQ];           // per-row entropy

// ---------------- reductions ----------------
__device__ __forceinline__ float warpReduceSum(float v) {
#pragma unroll
    for (int o = 16; o > 0; o >>= 1) v += __shfl_xor_sync(0xffffffffu, v, o);
    return v;
}
__device__ __forceinline__ float warpReduceMax(float v) {
#pragma unroll
    for (int o = 16; o > 0; o >>= 1) v = fmaxf(v, __shfl_xor_sync(0xffffffffu, v, o));
    return v;
}
__device__ __forceinline__ float blockReduceSum(float v) {
    __shared__ float sh[32];
    int lane = threadIdx.x & 31, w = threadIdx.x >> 5;
    v = warpReduceSum(v);
    if (lane == 0) sh[w] = v;
    __syncthreads();
    int nw = (blockDim.x + 31) >> 5;
    float r = (threadIdx.x < nw) ? sh[threadIdx.x] : 0.0f;
    if (w == 0) r = warpReduceSum(r);
    if (threadIdx.x == 0) sh[0] = r;
    __syncthreads();
    float out = sh[0];
    __syncthreads();
    return out;
}
__device__ __forceinline__ float blockReduceMax(float v) {
    __shared__ float sh[32];
    int lane = threadIdx.x & 31, w = threadIdx.x >> 5;
    v = warpReduceMax(v);
    if (lane == 0) sh[w] = v;
    __syncthreads();
    int nw = (blockDim.x + 31) >> 5;
    float r = (threadIdx.x < nw) ? sh[threadIdx.x] : -FLT_MAX;
    if (w == 0) r = warpReduceMax(r);
    if (threadIdx.x == 0) sh[0] = r;
    __syncthreads();
    float out = sh[0];
    __syncthreads();
    return out;
}

// ---------------- tiled SGEMM: C = alpha * A @ op(B) (+ bias) ----------------
// BM=BN=128, BK=16, 256 threads, 8x8 per-thread microtile.
// TB=false: B is [K,N] row-major (ldb=N). TB=true: B is [N,K] row-major (ldb=K), C = A @ B^T.
// All dims assumed multiples of tile sizes (true for this problem).
#define BM 128
#define BN 128
#define BK 16

template <bool TB, bool BIAS>
__global__ __launch_bounds__(256) void sgemm_kernel(
    const float* __restrict__ Ag, const float* __restrict__ Bg,
    const float* __restrict__ bias, float* __restrict__ Cg,
    int M, int N, int K,
    long sA, long sB, long sC, float alpha)
{
    const int bm = blockIdx.x * BM;
    const int bn = blockIdx.y * BN;
    const float* A = Ag + (long)blockIdx.z * sA;
    const float* B = Bg + (long)blockIdx.z * sB;
    float* C = Cg + (long)blockIdx.z * sC;

    __shared__ float As[BK][BM];
    __shared__ float Bs[BK][BN];

    const int tid = threadIdx.x;
    const int tx = tid & 15;   // column group
    const int ty = tid >> 4;   // row group

    float acc[8][8];
#pragma unroll
    for (int i = 0; i < 8; ++i)
#pragma unroll
        for (int j = 0; j < 8; ++j) acc[i][j] = 0.0f;

    for (int k0 = 0; k0 < K; k0 += BK) {
        // ---- load A tile: As[kk][m], float4 along K ----
#pragma unroll
        for (int it = 0; it < 2; ++it) {
            int slot = tid + it * 256;          // 512 float4 slots
            int m = slot >> 2;
            int k4 = (slot & 3) << 2;
            float4 v = *(const float4*)&A[(long)(bm + m) * K + k0 + k4];
            As[k4 + 0][m] = v.x; As[k4 + 1][m] = v.y;
            As[k4 + 2][m] = v.z; As[k4 + 3][m] = v.w;
        }
        // ---- load B tile: Bs[kk][n] ----
        if (TB) {
#pragma unroll
            for (int it = 0; it < 2; ++it) {
                int slot = tid + it * 256;
                int n = slot >> 2;
                int k4 = (slot & 3) << 2;
                float4 v = *(const float4*)&B[(long)(bn + n) * K + k0 + k4];
                Bs[k4 + 0][n] = v.x; Bs[k4 + 1][n] = v.y;
                Bs[k4 + 2][n] = v.z; Bs[k4 + 3][n] = v.w;
            }
        } else {
#pragma unroll
            for (int it = 0; it < 2; ++it) {
                int slot = tid + it * 256;
                int kk = slot >> 5;
                int n4 = (slot & 31) << 2;
                *(float4*)&Bs[kk][n4] = *(const float4*)&B[(long)(k0 + kk) * N + bn + n4];
            }
        }
        __syncthreads();

        // ---- compute ----
#pragma unroll
        for (int kk = 0; kk < BK; ++kk) {
            float a[8], b[8];
            *(float4*)&a[0] = *(const float4*)&As[kk][ty * 4];
            *(float4*)&a[4] = *(const float4*)&As[kk][64 + ty * 4];
            *(float4*)&b[0] = *(const float4*)&Bs[kk][tx * 4];
            *(float4*)&b[4] = *(const float4*)&Bs[kk][64 + tx * 4];
#pragma unroll
            for (int i = 0; i < 8; ++i)
#pragma unroll
                for (int j = 0; j < 8; ++j)
                    acc[i][j] += a[i] * b[j];
        }
        __syncthreads();
    }

    // ---- epilogue ----
#pragma unroll
    for (int i = 0; i < 8; ++i) {
        int r = bm + ((i < 4) ? (ty * 4 + i) : (64 + ty * 4 + (i - 4)));
#pragma unroll
        for (int jj = 0; jj < 2; ++jj) {
            int c = bn + ((jj == 0) ? (tx * 4) : (64 + tx * 4));
            float4 v;
            v.x = acc[i][jj * 4 + 0] * alpha;
            v.y = acc[i][jj * 4 + 1] * alpha;
            v.z = acc[i][jj * 4 + 2] * alpha;
            v.w = acc[i][jj * 4 + 3] * alpha;
            if (BIAS) {
                v.x += bias[c + 0]; v.y += bias[c + 1];
                v.z += bias[c + 2]; v.w += bias[c + 3];
            }
            *(float4*)&C[(long)r * N + c] = v;
        }
    }
}

// ---------------- softmax + entropy, one block per row of 2048 ----------------
__global__ __launch_bounds__(256) void softmax_entropy_kernel() {
    const long row = blockIdx.x;
    float* p = g_scores + row * (long)SEQ;
    const int tid = threadIdx.x;

    float x[8];
#pragma unroll
    for (int i = 0; i < 8; ++i) x[i] = p[tid + i * 256];

    float m = -FLT_MAX;
#pragma unroll
    for (int i = 0; i < 8; ++i) m = fmaxf(m, x[i]);
    m = blockReduceMax(m);

    float s = 0.0f;
#pragma unroll
    for (int i = 0; i < 8; ++i) { x[i] = expf(x[i] - m); s += x[i]; }
    s = blockReduceSum(s);
    float inv = 1.0f / s;

    float ent = 0.0f;
#pragma unroll
    for (int i = 0; i < 8; ++i) {
        float pv = x[i] * inv;
        p[tid + i * 256] = pv;
        ent -= pv * logf(pv + EPS_ENT);
    }
    ent = blockReduceSum(ent);
    if (tid == 0) g_rowent[row] = ent;
}

// ---------------- syntony: deterministic reduce of 16384 row entropies ----------------
__global__ __launch_bounds__(512) void syntony_kernel(float* __restrict__ out, long tail_off, int tail_cnt) {
    float s = 0.0f;
    const int nrows = BATCH * SEQ;
    for (int i = threadIdx.x; i < nrows; i += 512) s += g_rowent[i];
    s = blockReduceSum(s);
    if (threadIdx.x == 0) {
        float mean = s / (float)nrows;
        float syn = 1.0f - mean / logf((float)SEQ);
        syn = fminf(fmaxf(syn, 0.0f), 1.0f);
        for (int i = 0; i < tail_cnt; ++i) out[tail_off + i] = syn;
    }
}

// ---------------- layernorm in-place, one block per row of 1024 ----------------
__global__ __launch_bounds__(256) void layernorm_kernel(
    float* __restrict__ H, const float* __restrict__ gamma, const float* __restrict__ beta)
{
    const long row = blockIdx.x;
    float* h = H + row * (long)DMODEL;
    const int tid = threadIdx.x;

    float x[4];
#pragma unroll
    for (int i = 0; i < 4; ++i) x[i] = h[tid + i * 256];

    float s = x[0] + x[1] + x[2] + x[3];
    s = blockReduceSum(s);
    float mu = s * (1.0f / DMODEL);

    float v = 0.0f;
#pragma unroll
    for (int i = 0; i < 4; ++i) { float d = x[i] - mu; v += d * d; }
    v = blockReduceSum(v);
    float inv = rsqrtf(v * (1.0f / DMODEL) + EPS_LN);

#pragma unroll
    for (int i = 0; i < 4; ++i) {
        int c = tid + i * 256;
        h[c] = (x[i] - mu) * inv * gamma[c] + beta[c];
    }
}

// ---------------- launch ----------------
extern "C" void kernel_launch(void* const* d_in, const int* in_sizes, int n_in,
                              void* d_out, int out_size) {
    const float* q      = (const float*)d_in[0];
    const float* k      = (const float*)d_in[1];
    const float* v      = (const float*)d_in[2];
    const float* harm_w = (const float*)d_in[3];
    const float* harm_b = (const float*)d_in[4];
    const float* gamma  = (const float*)d_in[5];
    const float* beta   = (const float*)d_in[6];
    float* out = (float*)d_out;

    float* scores = nullptr;
    float* attout = nullptr;
    cudaGetSymbolAddress((void**)&scores, g_scores);
    cudaGetSymbolAddress((void**)&attout, g_attout);

    const long sQK = (long)SEQ * DMODEL;       // per-batch stride of q/k/v
    const long sS  = (long)SEQ * SEQ;          // per-batch stride of scores
    const long BSD = (long)BATCH * SEQ * DMODEL;

    // 1) scores = Q @ K^T / sqrt(D)
    {
        dim3 grid(SEQ / BM, SEQ / BN, BATCH);
        sgemm_kernel<true, false><<<grid, 256>>>(
            q, k, nullptr, scores, SEQ, SEQ, DMODEL, sQK, sQK, sS, 1.0f / 32.0f);
    }
    // 2) softmax + row entropy (in-place on scores)
    softmax_entropy_kernel<<<BATCH * SEQ, 256>>>();
    // 3) syntony scalar -> tail of d_out
    {
        int tail = (int)((long)out_size - BSD);
        if (tail > 0) syntony_kernel<<<1, 512>>>(out, BSD, tail);
    }
    // 4) attout = attention @ V
    {
        dim3 grid(SEQ / BM, DMODEL / BN, BATCH);
        sgemm_kernel<false, false><<<grid, 256>>>(
            scores, v, nullptr, attout, SEQ, DMODEL, SEQ, sS, sQK, sQK, 1.0f);
    }
    // 5) h = attout @ W + b  -> d_out
    {
        dim3 grid(SEQ / BM, DMODEL / BN, BATCH);
        sgemm_kernel<false, true><<<grid, 256>>>(
            attout, harm_w, harm_b, out, SEQ, DMODEL, DMODEL, sQK, 0L, sQK, 1.0f);
    }
    // 6) layernorm in-place on d_out
    layernorm_kernel<<<BATCH * SEQ, 256>>>(out, gamma, beta);
}

// round 3
// speedup vs baseline: 1.8811x; 1.8811x over previous
#include <cuda_runtime.h>
#include <cuda_bf16.h>
#include <cstdint>
#include <math.h>
#include <float.h>

// Problem constants
#define BATCH 8
#define SEQ   2048
#define DMODEL 1024
#define EPS_ENT 1e-10f
#define EPS_LN  1e-5f

// ---------------- scratch (allocation-free: __device__ globals) ----------------
__device__ float g_scores[(size_t)BATCH * SEQ * SEQ];     // 134 MB
__device__ float g_attout[(size_t)BATCH * SEQ * DMODEL];  // 67 MB
__device__ float g_rowent[(size_t)BATCH * SEQ];

// ---------------- tf32 helpers ----------------
__device__ __forceinline__ float to_tf32(float x) {
    uint32_t r;
    asm("cvt.rna.tf32.f32 %0, %1;" : "=r"(r) : "f"(x));
    return __uint_as_float(r);
}
__device__ __forceinline__ void mma_tf32(float c[4], const uint32_t a[4], const uint32_t b[2]) {
    asm volatile(
        "mma.sync.aligned.m16n8k8.row.col.f32.tf32.tf32.f32 "
        "{%0,%1,%2,%3}, {%4,%5,%6,%7}, {%8,%9}, {%0,%1,%2,%3};"
        : "+f"(c[0]), "+f"(c[1]), "+f"(c[2]), "+f"(c[3])
        : "r"(a[0]), "r"(a[1]), "r"(a[2]), "r"(a[3]), "r"(b[0]), "r"(b[1]));
}

// =====================================================================
// tf32 mma.sync GEMM:  C[M,N] = alpha * A[M,K] @ op(B) (+ bias)
//   TB=true : B is [N,K] row-major (C = A @ B^T)
//   TB=false: B is [K,N] row-major (C = A @ B)
// Block tile 128x128, BK=32, 256 threads = 8 warps (4 in M x 2 in N),
// warp tile 32x64 (2 m16-tiles x 8 n8-tiles). Double-buffered SMEM.
// All dims assumed multiples of tile sizes (true for this problem).
// =====================================================================
#define BM 128
#define BN 128
#define BKK 32
#define LDP 132                       // padded floats per k-row
#define TILE_F (BKK * LDP)            // 4224 floats per tile

template <bool TB, bool BIAS>
__global__ __launch_bounds__(256, 1) void mma_gemm_kernel(
    const float* __restrict__ Ag, const float* __restrict__ Bg,
    const float* __restrict__ bias, float* __restrict__ Cg,
    int K, long lda, long ldb, long ldc,
    long sA, long sB, long sC, float alpha)
{
    extern __shared__ float sm[];   // 4 tiles: [A0 B0 A1 B1]

    const int tid = threadIdx.x;
    const int wid = tid >> 5;
    const int lid = tid & 31;
    const int wm = wid & 3;          // warp M position (0..3)
    const int wn = wid >> 2;         // warp N position (0..1)
    const int g = lid >> 2;          // group id (0..7)
    const int t = lid & 3;           // thread-in-group (0..3)

    const long bm = (long)blockIdx.x * BM;
    const long bn = (long)blockIdx.y * BN;
    const float* A = Ag + (long)blockIdx.z * sA;
    const float* B = Bg + (long)blockIdx.z * sB;
    float* C = Cg + (long)blockIdx.z * sC;

    float acc[2][8][4];
#pragma unroll
    for (int mt = 0; mt < 2; ++mt)
#pragma unroll
        for (int nt = 0; nt < 8; ++nt)
#pragma unroll
            for (int c = 0; c < 4; ++c) acc[mt][nt][c] = 0.0f;

    float4 ra[4], rb[4];

    // ---- gmem -> regs for chunk at k0 ----
    auto load_regs = [&](long k0) {
#pragma unroll
        for (int it = 0; it < 4; ++it) {
            int slot = tid + it * 256;     // 1024 float4 slots: A is 128 rows x 8 float4
            ra[it] = *(const float4*)&A[(bm + (slot >> 3)) * lda + k0 + ((slot & 7) << 2)];
        }
        if (TB) {
#pragma unroll
            for (int it = 0; it < 4; ++it) {
                int slot = tid + it * 256; // B: 128 rows (n) x 8 float4 (k)
                rb[it] = *(const float4*)&B[(bn + (slot >> 3)) * ldb + k0 + ((slot & 7) << 2)];
            }
        } else {
#pragma unroll
            for (int it = 0; it < 4; ++it) {
                int slot = tid + it * 256; // B: 32 rows (k) x 32 float4 (n)
                rb[it] = *(const float4*)&B[(k0 + (slot >> 5)) * ldb + bn + ((slot & 31) << 2)];
            }
        }
    };

    // ---- regs -> smem stage (with tf32 rounding) ----
    auto store_regs = [&](int s) {
        float* As_ = sm + s * 2 * TILE_F;
        float* Bs_ = As_ + TILE_F;
#pragma unroll
        for (int it = 0; it < 4; ++it) {
            int slot = tid + it * 256;
            int m = slot >> 3, k4 = (slot & 7) << 2;
            As_[(k4 + 0) * LDP + m] = to_tf32(ra[it].x);
            As_[(k4 + 1) * LDP + m] = to_tf32(ra[it].y);
            As_[(k4 + 2) * LDP + m] = to_tf32(ra[it].z);
            As_[(k4 + 3) * LDP + m] = to_tf32(ra[it].w);
        }
        if (TB) {
#pragma unroll
            for (int it = 0; it < 4; ++it) {
                int slot = tid + it * 256;
                int n = slot >> 3, k4 = (slot & 7) << 2;
                Bs_[(k4 + 0) * LDP + n] = to_tf32(rb[it].x);
                Bs_[(k4 + 1) * LDP + n] = to_tf32(rb[it].y);
                Bs_[(k4 + 2) * LDP + n] = to_tf32(rb[it].z);
                Bs_[(k4 + 3) * LDP + n] = to_tf32(rb[it].w);
            }
        } else {
#pragma unroll
            for (int it = 0; it < 4; ++it) {
                int slot = tid + it * 256;
                int k = slot >> 5, n4 = (slot & 31) << 2;
                float4 v;
                v.x = to_tf32(rb[it].x); v.y = to_tf32(rb[it].y);
                v.z = to_tf32(rb[it].z); v.w = to_tf32(rb[it].w);
                *(float4*)&Bs_[k * LDP + n4] = v;
            }
        }
    };

    // ---- compute one BK=32 chunk from smem stage ----
    auto compute = [&](int s) {
        const float* As_ = sm + s * 2 * TILE_F;
        const float* Bs_ = As_ + TILE_F;
#pragma unroll
        for (int ks = 0; ks < 4; ++ks) {
            const int kb = ks * 8;
            uint32_t a[2][4], b[8][2];
#pragma unroll
            for (int mt = 0; mt < 2; ++mt) {
                const int m0 = wm * 32 + mt * 16;
                a[mt][0] = __float_as_uint(As_[(kb + t) * LDP + m0 + g]);
                a[mt][1] = __float_as_uint(As_[(kb + t) * LDP + m0 + g + 8]);
                a[mt][2] = __float_as_uint(As_[(kb + t + 4) * LDP + m0 + g]);
                a[mt][3] = __float_as_uint(As_[(kb + t + 4) * LDP + m0 + g + 8]);
            }
#pragma unroll
            for (int nt = 0; nt < 8; ++nt) {
                const int n0 = wn * 64 + nt * 8;
                b[nt][0] = __float_as_uint(Bs_[(kb + t) * LDP + n0 + g]);
                b[nt][1] = __float_as_uint(Bs_[(kb + t + 4) * LDP + n0 + g]);
            }
#pragma unroll
            for (int mt = 0; mt < 2; ++mt)
#pragma unroll
                for (int nt = 0; nt < 8; ++nt)
                    mma_tf32(acc[mt][nt], a[mt], b[nt]);
        }
    };

    const int nch = K / BKK;
    load_regs(0);
    store_regs(0);
    __syncthreads();
    for (int i = 0; i < nch; ++i) {
        const int s = i & 1;
        if (i + 1 < nch) load_regs((long)(i + 1) * BKK);
        compute(s);
        __syncthreads();
        if (i + 1 < nch) {
            store_regs(s ^ 1);
            __syncthreads();
        }
    }

    // ---- epilogue ----
#pragma unroll
    for (int mt = 0; mt < 2; ++mt) {
        const long mrow = bm + wm * 32 + mt * 16;
#pragma unroll
        for (int nt = 0; nt < 8; ++nt) {
            const long col = bn + wn * 64 + nt * 8 + 2 * t;
            float2 v0, v1;
            v0.x = acc[mt][nt][0] * alpha; v0.y = acc[mt][nt][1] * alpha;
            v1.x = acc[mt][nt][2] * alpha; v1.y = acc[mt][nt][3] * alpha;
            if (BIAS) {
                float b0 = bias[col], b1 = bias[col + 1];
                v0.x += b0; v0.y += b1; v1.x += b0; v1.y += b1;
            }
            *(float2*)&C[(mrow + g) * ldc + col] = v0;
            *(float2*)&C[(mrow + g + 8) * ldc + col] = v1;
        }
    }
}

#define GEMM_SMEM_BYTES (4 * TILE_F * sizeof(float))   // 67584

// =====================================================================
// reductions + softmax/entropy + syntony + layernorm
// =====================================================================
__device__ __forceinline__ float warpReduceSum(float v) {
#pragma unroll
    for (int o = 16; o > 0; o >>= 1) v += __shfl_xor_sync(0xffffffffu, v, o);
    return v;
}
__device__ __forceinline__ float warpReduceMax(float v) {
#pragma unroll
    for (int o = 16; o > 0; o >>= 1) v = fmaxf(v, __shfl_xor_sync(0xffffffffu, v, o));
    return v;
}
__device__ __forceinline__ float blockReduceSum(float v) {
    __shared__ float sh[32];
    int lane = threadIdx.x & 31, w = threadIdx.x >> 5;
    v = warpReduceSum(v);
    if (lane == 0) sh[w] = v;
    __syncthreads();
    int nw = (blockDim.x + 31) >> 5;
    float r = (threadIdx.x < nw) ? sh[threadIdx.x] : 0.0f;
    if (w == 0) r = warpReduceSum(r);
    if (threadIdx.x == 0) sh[0] = r;
    __syncthreads();
    float out = sh[0];
    __syncthreads();
    return out;
}
__device__ __forceinline__ float blockReduceMax(float v) {
    __shared__ float sh[32];
    int lane = threadIdx.x & 31, w = threadIdx.x >> 5;
    v = warpReduceMax(v);
    if (lane == 0) sh[w] = v;
    __syncthreads();
    int nw = (blockDim.x + 31) >> 5;
    float r = (threadIdx.x < nw) ? sh[threadIdx.x] : -FLT_MAX;
    if (w == 0) r = warpReduceMax(r);
    if (threadIdx.x == 0) sh[0] = r;
    __syncthreads();
    float out = sh[0];
    __syncthreads();
    return out;
}

__global__ __launch_bounds__(256) void softmax_entropy_kernel() {
    const long row = blockIdx.x;
    float* p = g_scores + row * (long)SEQ;
    const int tid = threadIdx.x;
    float x[8];
#pragma unroll
    for (int i = 0; i < 8; ++i) x[i] = p[tid + i * 256];
    float m = -FLT_MAX;
#pragma unroll
    for (int i = 0; i < 8; ++i) m = fmaxf(m, x[i]);
    m = blockReduceMax(m);
    float s = 0.0f;
#pragma unroll
    for (int i = 0; i < 8; ++i) { x[i] = expf(x[i] - m); s += x[i]; }
    s = blockReduceSum(s);
    float inv = 1.0f / s;
    float ent = 0.0f;
#pragma unroll
    for (int i = 0; i < 8; ++i) {
        float pv = x[i] * inv;
        p[tid + i * 256] = pv;
        ent -= pv * logf(pv + EPS_ENT);
    }
    ent = blockReduceSum(ent);
    if (tid == 0) g_rowent[row] = ent;
}

__global__ __launch_bounds__(512) void syntony_kernel(float* __restrict__ out, long tail_off, int tail_cnt) {
    float s = 0.0f;
    const int nrows = BATCH * SEQ;
    for (int i = threadIdx.x; i < nrows; i += 512) s += g_rowent[i];
    s = blockReduceSum(s);
    if (threadIdx.x == 0) {
        float mean = s / (float)nrows;
        float syn = 1.0f - mean / logf((float)SEQ);
        syn = fminf(fmaxf(syn, 0.0f), 1.0f);
        for (int i = 0; i < tail_cnt; ++i) out[tail_off + i] = syn;
    }
}

__global__ __launch_bounds__(256) void layernorm_kernel(
    float* __restrict__ H, const float* __restrict__ gamma, const float* __restrict__ beta)
{
    const long row = blockIdx.x;
    float* h = H + row * (long)DMODEL;
    const int tid = threadIdx.x;
    float x[4];
#pragma unroll
    for (int i = 0; i < 4; ++i) x[i] = h[tid + i * 256];
    float s = x[0] + x[1] + x[2] + x[3];
    s = blockReduceSum(s);
    float mu = s * (1.0f / DMODEL);
    float v = 0.0f;
#pragma unroll
    for (int i = 0; i < 4; ++i) { float d = x[i] - mu; v += d * d; }
    v = blockReduceSum(v);
    float inv = rsqrtf(v * (1.0f / DMODEL) + EPS_LN);
#pragma unroll
    for (int i = 0; i < 4; ++i) {
        int c = tid + i * 256;
        h[c] = (x[i] - mu) * inv * gamma[c] + beta[c];
    }
}

// =====================================================================
// launch
// =====================================================================
extern "C" void kernel_launch(void* const* d_in, const int* in_sizes, int n_in,
                              void* d_out, int out_size) {
    const float* q      = (const float*)d_in[0];
    const float* k      = (const float*)d_in[1];
    const float* v      = (const float*)d_in[2];
    const float* harm_w = (const float*)d_in[3];
    const float* harm_b = (const float*)d_in[4];
    const float* gamma  = (const float*)d_in[5];
    const float* beta   = (const float*)d_in[6];
    float* out = (float*)d_out;

    float *scores, *attout;
    cudaGetSymbolAddress((void**)&scores, g_scores);
    cudaGetSymbolAddress((void**)&attout, g_attout);

    cudaFuncSetAttribute(mma_gemm_kernel<true, false>,  cudaFuncAttributeMaxDynamicSharedMemorySize, GEMM_SMEM_BYTES);
    cudaFuncSetAttribute(mma_gemm_kernel<false, false>, cudaFuncAttributeMaxDynamicSharedMemorySize, GEMM_SMEM_BYTES);
    cudaFuncSetAttribute(mma_gemm_kernel<false, true>,  cudaFuncAttributeMaxDynamicSharedMemorySize, GEMM_SMEM_BYTES);

    const long sQK = (long)SEQ * DMODEL;
    const long sS  = (long)SEQ * SEQ;
    const long BSD = (long)BATCH * SEQ * DMODEL;

    // 1) scores = (Q @ K^T) / 32
    {
        dim3 grid(SEQ / BM, SEQ / BN, BATCH);
        mma_gemm_kernel<true, false><<<grid, 256, GEMM_SMEM_BYTES>>>(
            q, k, nullptr, scores, DMODEL, DMODEL, DMODEL, SEQ, sQK, sQK, sS, 1.0f / 32.0f);
    }
    // 2) softmax + row entropy (in-place)
    softmax_entropy_kernel<<<BATCH * SEQ, 256>>>();
    // 3) syntony scalar -> tail of d_out
    {
        int tail = (int)((long)out_size - BSD);
        if (tail > 0) syntony_kernel<<<1, 512>>>(out, BSD, tail);
    }
    // 4) attout = P @ V   (B = V is [K=SEQ, N=DMODEL])
    {
        dim3 grid(SEQ / BM, DMODEL / BN, BATCH);
        mma_gemm_kernel<false, false><<<grid, 256, GEMM_SMEM_BYTES>>>(
            scores, v, nullptr, attout, SEQ, SEQ, DMODEL, DMODEL, sS, sQK, sQK, 1.0f);
    }
    // 5) h = attout @ W + b   (B = W is [K=DMODEL, N=DMODEL]) -> d_out
    {
        dim3 grid((BATCH * SEQ) / BM, DMODEL / BN, 1);
        mma_gemm_kernel<false, true><<<grid, 256, GEMM_SMEM_BYTES>>>(
            attout, harm_w, harm_b, out, DMODEL, DMODEL, DMODEL, DMODEL, 0L, 0L, 0L, 1.0f);
    }
    // 6) layernorm in-place on d_out
    layernorm_kernel<<<BATCH * SEQ, 256>>>(out, gamma, beta);
}

// round 4
// speedup vs baseline: 2.5052x; 1.3318x over previous
#include <cuda_runtime.h>
#include <cuda_bf16.h>
#include <cstdint>
#include <math.h>
#include <float.h>

// Problem constants
#define BATCH 8
#define SEQ   2048
#define DMODEL 1024
#define EPS_ENT 1e-10f
#define EPS_LN  1e-5f

// ---------------- scratch (allocation-free: __device__ globals) ----------------
__device__ float g_scores[(size_t)BATCH * SEQ * SEQ];     // 134 MB
__device__ float g_attout[(size_t)BATCH * SEQ * DMODEL];  // 67 MB
__device__ float g_rowent[(size_t)BATCH * SEQ];

// ---------------- tf32 helpers ----------------
__device__ __forceinline__ float to_tf32(float x) {
    uint32_t r;
    asm("cvt.rna.tf32.f32 %0, %1;" : "=r"(r) : "f"(x));
    return __uint_as_float(r);
}
__device__ __forceinline__ void mma_tf32(float c[4], const uint32_t a[4], const uint32_t b[2]) {
    asm volatile(
        "mma.sync.aligned.m16n8k8.row.col.f32.tf32.tf32.f32 "
        "{%0,%1,%2,%3}, {%4,%5,%6,%7}, {%8,%9}, {%0,%1,%2,%3};"
        : "+f"(c[0]), "+f"(c[1]), "+f"(c[2]), "+f"(c[3])
        : "r"(a[0]), "r"(a[1]), "r"(a[2]), "r"(a[3]), "r"(b[0]), "r"(b[1]));
}

// =====================================================================
// tf32 mma.sync GEMM:  C[M,N] = alpha * A[M,K] @ op(B) (+ bias)
//   TB=true : B is [N,K] row-major (C = A @ B^T)
//   TB=false: B is [K,N] row-major (C = A @ B)
// Block tile 128x128, BK=32, 256 threads = 8 warps (4 M x 2 N),
// warp tile 32x64. Double-buffered SMEM.
// SMEM tiles are [row][k] with LDK=36 pad -> fragment loads hit banks
// (4g+t) mod 32 = all distinct (conflict-free).
// =====================================================================
#define BM 128
#define BN 128
#define BKK 32
#define LDK 36                         // floats per SMEM row (32 + 4 pad)
#define TILE_F (128 * LDK)             // 4608 floats per tile

template <bool TB, bool BIAS>
__global__ __launch_bounds__(256, 1) void mma_gemm_kernel(
    const float* __restrict__ Ag, const float* __restrict__ Bg,
    const float* __restrict__ bias, float* __restrict__ Cg,
    int K, long lda, long ldb, long ldc,
    long sA, long sB, long sC, float alpha)
{
    extern __shared__ float sm[];   // [A0 B0 A1 B1], each TILE_F floats

    const int tid = threadIdx.x;
    const int wid = tid >> 5;
    const int lid = tid & 31;
    const int wm = wid & 3;          // warp M position (0..3)
    const int wn = wid >> 2;         // warp N position (0..1)
    const int g = lid >> 2;          // group id (0..7)
    const int t = lid & 3;           // thread-in-group (0..3)

    const long bm = (long)blockIdx.x * BM;
    const long bn = (long)blockIdx.y * BN;
    const float* A = Ag + (long)blockIdx.z * sA;
    const float* B = Bg + (long)blockIdx.z * sB;
    float* C = Cg + (long)blockIdx.z * sC;

    float acc[2][8][4];
#pragma unroll
    for (int mt = 0; mt < 2; ++mt)
#pragma unroll
        for (int nt = 0; nt < 8; ++nt)
#pragma unroll
            for (int c = 0; c < 4; ++c) acc[mt][nt][c] = 0.0f;

    float4 ra[4], rb[4];

    // ---- gmem -> regs for chunk at k0 ----
    auto load_regs = [&](long k0) {
#pragma unroll
        for (int it = 0; it < 4; ++it) {
            int slot = tid + it * 256;     // A: 128 rows x 8 float4 along k
            ra[it] = *(const float4*)&A[(bm + (slot >> 3)) * lda + k0 + ((slot & 7) << 2)];
        }
        if (TB) {
#pragma unroll
            for (int it = 0; it < 4; ++it) {
                int slot = tid + it * 256; // B: 128 rows (n) x 8 float4 (k)
                rb[it] = *(const float4*)&B[(bn + (slot >> 3)) * ldb + k0 + ((slot & 7) << 2)];
            }
        } else {
            // B is [K,N]; gather 4 k-rows per lane (each row access is 128B-coalesced per warp)
#pragma unroll
            for (int it = 0; it < 4; ++it) {
                int slot = tid + it * 256;
                int n = slot & 127;
                int kq = slot >> 7;        // 0..7
                const float* bp = &B[(k0 + kq * 4) * ldb + bn + n];
                rb[it].x = bp[0];
                rb[it].y = bp[ldb];
                rb[it].z = bp[2 * ldb];
                rb[it].w = bp[3 * ldb];
            }
        }
    };

    // ---- regs -> smem stage (tf32 rounding; STS.128, conflict-free) ----
    auto store_regs = [&](int s) {
        float* As_ = sm + s * 2 * TILE_F;
        float* Bs_ = As_ + TILE_F;
#pragma unroll
        for (int it = 0; it < 4; ++it) {
            int slot = tid + it * 256;
            int m = slot >> 3, k4 = (slot & 7) << 2;
            float4 v;
            v.x = to_tf32(ra[it].x); v.y = to_tf32(ra[it].y);
            v.z = to_tf32(ra[it].z); v.w = to_tf32(ra[it].w);
            *(float4*)&As_[m * LDK + k4] = v;
        }
        if (TB) {
#pragma unroll
            for (int it = 0; it < 4; ++it) {
                int slot = tid + it * 256;
                int n = slot >> 3, k4 = (slot & 7) << 2;
                float4 v;
                v.x = to_tf32(rb[it].x); v.y = to_tf32(rb[it].y);
                v.z = to_tf32(rb[it].z); v.w = to_tf32(rb[it].w);
                *(float4*)&Bs_[n * LDK + k4] = v;
            }
        } else {
#pragma unroll
            for (int it = 0; it < 4; ++it) {
                int slot = tid + it * 256;
                int n = slot & 127, k4 = (slot >> 7) << 2;
                float4 v;
                v.x = to_tf32(rb[it].x); v.y = to_tf32(rb[it].y);
                v.z = to_tf32(rb[it].z); v.w = to_tf32(rb[it].w);
                *(float4*)&Bs_[n * LDK + k4] = v;
            }
        }
    };

    // ---- compute one BK=32 chunk from smem stage ----
    auto compute = [&](int s) {
        const float* As_ = sm + s * 2 * TILE_F;
        const float* Bs_ = As_ + TILE_F;
#pragma unroll
        for (int ks = 0; ks < 4; ++ks) {
            const int kb = ks * 8;
            uint32_t a[2][4], b[8][2];
#pragma unroll
            for (int mt = 0; mt < 2; ++mt) {
                const int m0 = wm * 32 + mt * 16;
                a[mt][0] = __float_as_uint(As_[(m0 + g) * LDK + kb + t]);
                a[mt][1] = __float_as_uint(As_[(m0 + g + 8) * LDK + kb + t]);
                a[mt][2] = __float_as_uint(As_[(m0 + g) * LDK + kb + t + 4]);
                a[mt][3] = __float_as_uint(As_[(m0 + g + 8) * LDK + kb + t + 4]);
            }
#pragma unroll
            for (int nt = 0; nt < 8; ++nt) {
                const int n0 = wn * 64 + nt * 8;
                b[nt][0] = __float_as_uint(Bs_[(n0 + g) * LDK + kb + t]);
                b[nt][1] = __float_as_uint(Bs_[(n0 + g) * LDK + kb + t + 4]);
            }
#pragma unroll
            for (int mt = 0; mt < 2; ++mt)
#pragma unroll
                for (int nt = 0; nt < 8; ++nt)
                    mma_tf32(acc[mt][nt], a[mt], b[nt]);
        }
    };

    const int nch = K / BKK;
    load_regs(0);
    store_regs(0);
    __syncthreads();
    for (int i = 0; i < nch; ++i) {
        const int s = i & 1;
        if (i + 1 < nch) load_regs((long)(i + 1) * BKK);
        compute(s);
        __syncthreads();
        if (i + 1 < nch) {
            store_regs(s ^ 1);
            __syncthreads();
        }
    }

    // ---- epilogue ----
#pragma unroll
    for (int mt = 0; mt < 2; ++mt) {
        const long mrow = bm + wm * 32 + mt * 16;
#pragma unroll
        for (int nt = 0; nt < 8; ++nt) {
            const long col = bn + wn * 64 + nt * 8 + 2 * t;
            float2 v0, v1;
            v0.x = acc[mt][nt][0] * alpha; v0.y = acc[mt][nt][1] * alpha;
            v1.x = acc[mt][nt][2] * alpha; v1.y = acc[mt][nt][3] * alpha;
            if (BIAS) {
                float b0 = bias[col], b1 = bias[col + 1];
                v0.x += b0; v0.y += b1; v1.x += b0; v1.y += b1;
            }
            *(float2*)&C[(mrow + g) * ldc + col] = v0;
            *(float2*)&C[(mrow + g + 8) * ldc + col] = v1;
        }
    }
}

#define GEMM_SMEM_BYTES (4 * TILE_F * sizeof(float))   // 73728

// =====================================================================
// reductions + softmax/entropy + syntony + layernorm
// =====================================================================
__device__ __forceinline__ float warpReduceSum(float v) {
#pragma unroll
    for (int o = 16; o > 0; o >>= 1) v += __shfl_xor_sync(0xffffffffu, v, o);
    return v;
}
__device__ __forceinline__ float warpReduceMax(float v) {
#pragma unroll
    for (int o = 16; o > 0; o >>= 1) v = fmaxf(v, __shfl_xor_sync(0xffffffffu, v, o));
    return v;
}
__device__ __forceinline__ float blockReduceSum(float v) {
    __shared__ float sh[32];
    int lane = threadIdx.x & 31, w = threadIdx.x >> 5;
    v = warpReduceSum(v);
    if (lane == 0) sh[w] = v;
    __syncthreads();
    int nw = (blockDim.x + 31) >> 5;
    float r = (threadIdx.x < nw) ? sh[threadIdx.x] : 0.0f;
    if (w == 0) r = warpReduceSum(r);
    if (threadIdx.x == 0) sh[0] = r;
    __syncthreads();
    float out = sh[0];
    __syncthreads();
    return out;
}
__device__ __forceinline__ float blockReduceMax(float v) {
    __shared__ float sh[32];
    int lane = threadIdx.x & 31, w = threadIdx.x >> 5;
    v = warpReduceMax(v);
    if (lane == 0) sh[w] = v;
    __syncthreads();
    int nw = (blockDim.x + 31) >> 5;
    float r = (threadIdx.x < nw) ? sh[threadIdx.x] : -FLT_MAX;
    if (w == 0) r = warpReduceMax(r);
    if (threadIdx.x == 0) sh[0] = r;
    __syncthreads();
    float out = sh[0];
    __syncthreads();
    return out;
}

__global__ __launch_bounds__(256) void softmax_entropy_kernel() {
    const long row = blockIdx.x;
    float* p = g_scores + row * (long)SEQ;
    const int tid = threadIdx.x;
    float x[8];
#pragma unroll
    for (int i = 0; i < 8; ++i) x[i] = p[tid + i * 256];
    float m = -FLT_MAX;
#pragma unroll
    for (int i = 0; i < 8; ++i) m = fmaxf(m, x[i]);
    m = blockReduceMax(m);
    float s = 0.0f;
#pragma unroll
    for (int i = 0; i < 8; ++i) { x[i] = expf(x[i] - m); s += x[i]; }
    s = blockReduceSum(s);
    float inv = 1.0f / s;
    float ent = 0.0f;
#pragma unroll
    for (int i = 0; i < 8; ++i) {
        float pv = x[i] * inv;
        p[tid + i * 256] = pv;
        ent -= pv * logf(pv + EPS_ENT);
    }
    ent = blockReduceSum(ent);
    if (tid == 0) g_rowent[row] = ent;
}

__global__ __launch_bounds__(512) void syntony_kernel(float* __restrict__ out, long tail_off, int tail_cnt) {
    float s = 0.0f;
    const int nrows = BATCH * SEQ;
    for (int i = threadIdx.x; i < nrows; i += 512) s += g_rowent[i];
    s = blockReduceSum(s);
    if (threadIdx.x == 0) {
        float mean = s / (float)nrows;
        float syn = 1.0f - mean / logf((float)SEQ);
        syn = fminf(fmaxf(syn, 0.0f), 1.0f);
        for (int i = 0; i < tail_cnt; ++i) out[tail_off + i] = syn;
    }
}

__global__ __launch_bounds__(256) void layernorm_kernel(
    float* __restrict__ H, const float* __restrict__ gamma, const float* __restrict__ beta)
{
    const long row = blockIdx.x;
    float* h = H + row * (long)DMODEL;
    const int tid = threadIdx.x;
    float x[4];
#pragma unroll
    for (int i = 0; i < 4; ++i) x[i] = h[tid + i * 256];
    float s = x[0] + x[1] + x[2] + x[3];
    s = blockReduceSum(s);
    float mu = s * (1.0f / DMODEL);
    float v = 0.0f;
#pragma unroll
    for (int i = 0; i < 4; ++i) { float d = x[i] - mu; v += d * d; }
    v = blockReduceSum(v);
    float inv = rsqrtf(v * (1.0f / DMODEL) + EPS_LN);
#pragma unroll
    for (int i = 0; i < 4; ++i) {
        int c = tid + i * 256;
        h[c] = (x[i] - mu) * inv * gamma[c] + beta[c];
    }
}

// =====================================================================
// launch
// =====================================================================
extern "C" void kernel_launch(void* const* d_in, const int* in_sizes, int n_in,
                              void* d_out, int out_size) {
    const float* q      = (const float*)d_in[0];
    const float* k      = (const float*)d_in[1];
    const float* v      = (const float*)d_in[2];
    const float* harm_w = (const float*)d_in[3];
    const float* harm_b = (const float*)d_in[4];
    const float* gamma  = (const float*)d_in[5];
    const float* beta   = (const float*)d_in[6];
    float* out = (float*)d_out;

    float *scores, *attout;
    cudaGetSymbolAddress((void**)&scores, g_scores);
    cudaGetSymbolAddress((void**)&attout, g_attout);

    cudaFuncSetAttribute(mma_gemm_kernel<true, false>,  cudaFuncAttributeMaxDynamicSharedMemorySize, GEMM_SMEM_BYTES);
    cudaFuncSetAttribute(mma_gemm_kernel<false, false>, cudaFuncAttributeMaxDynamicSharedMemorySize, GEMM_SMEM_BYTES);
    cudaFuncSetAttribute(mma_gemm_kernel<false, true>,  cudaFuncAttributeMaxDynamicSharedMemorySize, GEMM_SMEM_BYTES);

    const long sQK = (long)SEQ * DMODEL;
    const long sS  = (long)SEQ * SEQ;
    const long BSD = (long)BATCH * SEQ * DMODEL;

    // 1) scores = (Q @ K^T) / 32
    {
        dim3 grid(SEQ / BM, SEQ / BN, BATCH);
        mma_gemm_kernel<true, false><<<grid, 256, GEMM_SMEM_BYTES>>>(
            q, k, nullptr, scores, DMODEL, DMODEL, DMODEL, SEQ, sQK, sQK, sS, 1.0f / 32.0f);
    }
    // 2) softmax + row entropy (in-place)
    softmax_entropy_kernel<<<BATCH * SEQ, 256>>>();
    // 3) syntony scalar -> tail of d_out
    {
        int tail = (int)((long)out_size - BSD);
        if (tail > 0) syntony_kernel<<<1, 512>>>(out, BSD, tail);
    }
    // 4) attout = P @ V   (B = V is [K=SEQ, N=DMODEL])
    {
        dim3 grid(SEQ / BM, DMODEL / BN, BATCH);
        mma_gemm_kernel<false, false><<<grid, 256, GEMM_SMEM_BYTES>>>(
            scores, v, nullptr, attout, SEQ, SEQ, DMODEL, DMODEL, sS, sQK, sQK, 1.0f);
    }
    // 5) h = attout @ W + b   (B = W is [K=DMODEL, N=DMODEL]) -> d_out
    {
        dim3 grid((BATCH * SEQ) / BM, DMODEL / BN, 1);
        mma_gemm_kernel<false, true><<<grid, 256, GEMM_SMEM_BYTES>>>(
            attout, harm_w, harm_b, out, DMODEL, DMODEL, DMODEL, DMODEL, 0L, 0L, 0L, 1.0f);
    }
    // 6) layernorm in-place on d_out
    layernorm_kernel<<<BATCH * SEQ, 256>>>(out, gamma, beta);
}